// round 4
// baseline (speedup 1.0000x reference)
#include <cuda_runtime.h>
#include <cuda_bf16.h>

#define INV_SQRT2 0.70710678118654752440f

// Dynamic smem layout (floats), all bases 16B-aligned:
//   sx  @ 0      len 4104 : x[t]  at sx[t+4],  zeros [0..3], [4100..4103]
//   sL0 @ 4104   len 2056 : xL[i] at +4,       zeros [0..3], [2052..2055]
//   sL1 @ 6160   len 2056
//   sH0 @ 8216   len 2056 : xH[i] at +4,       zeros [0..3], [2052..2055]
//   sH1 @ 10272  len 2056
#define SMEM_FLOATS 12328

__device__ __forceinline__ float gelu_leaky(float a) {
    float t = 0.5f * a;
    a = fmaf(t, erff(a * INV_SQRT2), t);   // exact GELU
    return fmaxf(a, 0.01f * a);            // LeakyReLU(0.01)
}

// One CTA per (b, cin); produces output channels 2*cin, 2*cin+1.
// BN scale folded into w1; both 1/sqrt2 factors folded into w2L/w2H (=> w/2).
__global__ __launch_bounds__(256, 4)
void fused_block_wavelet_down(
    const float* __restrict__ x,      // (64, 64, 4096)
    const float* __restrict__ w1,     // (128, 1, 7)
    const float* __restrict__ g1,
    const float* __restrict__ b1,
    const float* __restrict__ m1,
    const float* __restrict__ v1,
    const float* __restrict__ w2L,    // (128, 1, 7)
    const float* __restrict__ w2H,    // (128, 1, 3)
    const float* __restrict__ wskip,  // (128, 1, 1)
    float* __restrict__ out)          // (64, 128, 4096)
{
    extern __shared__ float smem[];
    float* sx  = smem;
    float* sL0 = smem + 4104;
    float* sL1 = smem + 6160;
    float* sH0 = smem + 8216;
    float* sH1 = smem + 10272;

    const int tid = threadIdx.x;
    const int b   = blockIdx.x >> 6;
    const int cin = blockIdx.x & 63;
    const int oc0 = 2 * cin;

    // zero pad cells
    if (tid == 0) *reinterpret_cast<float4*>(sx)          = make_float4(0,0,0,0);
    if (tid == 1) *reinterpret_cast<float4*>(sx + 4100)   = make_float4(0,0,0,0);
    if (tid == 2) *reinterpret_cast<float4*>(sL0)         = make_float4(0,0,0,0);
    if (tid == 3) *reinterpret_cast<float4*>(sL0 + 2052)  = make_float4(0,0,0,0);
    if (tid == 4) *reinterpret_cast<float4*>(sL1)         = make_float4(0,0,0,0);
    if (tid == 5) *reinterpret_cast<float4*>(sL1 + 2052)  = make_float4(0,0,0,0);
    if (tid == 6) *reinterpret_cast<float4*>(sH0)         = make_float4(0,0,0,0);
    if (tid == 7) *reinterpret_cast<float4*>(sH0 + 2052)  = make_float4(0,0,0,0);
    if (tid == 8) *reinterpret_cast<float4*>(sH1)         = make_float4(0,0,0,0);
    if (tid == 9) *reinterpret_cast<float4*>(sH1 + 2052)  = make_float4(0,0,0,0);

    // load x row: LDG.128 -> STS.128, lane-contiguous
    {
        const float4* x4 = reinterpret_cast<const float4*>(
            x + ((size_t)(b * 64 + cin) << 12));
        float4* sxw = reinterpret_cast<float4*>(sx + 4);
        #pragma unroll
        for (int p = 0; p < 4; ++p)
            sxw[tid + p * 256] = x4[tid + p * 256];
    }

    // phase-1 weights, BN folded: h = conv(x, w1*inv) + bias
    float wk0[7], wk1[7];
    const float inv0 = g1[oc0]     * rsqrtf(v1[oc0]     + 1e-5f);
    const float inv1 = g1[oc0 + 1] * rsqrtf(v1[oc0 + 1] + 1e-5f);
    #pragma unroll
    for (int k = 0; k < 7; ++k) {
        wk0[k] = w1[oc0 * 7 + k]     * inv0;
        wk1[k] = w1[oc0 * 7 + 7 + k] * inv1;
    }
    const float bias0 = b1[oc0]     - m1[oc0]     * inv0;
    const float bias1 = b1[oc0 + 1] - m1[oc0 + 1] * inv1;

    __syncthreads();

    const float4* sx4  = reinterpret_cast<const float4*>(sx);
    float4* sL04 = reinterpret_cast<float4*>(sL0);
    float4* sL14 = reinterpret_cast<float4*>(sL1);
    float4* sH04 = reinterpret_cast<float4*>(sH0);
    float4* sH14 = reinterpret_cast<float4*>(sH1);

    // ---- phase 1: 8 h-values / thread-iter, both channels, unscaled Haar ----
    #pragma unroll 1
    for (int p = 0; p < 2; ++p) {
        const int tp = tid + p * 256;          // h base = 8*tp, pair base = 4*tp
        float4 f0 = sx4[2 * tp + 0];
        float4 f1 = sx4[2 * tp + 1];
        float4 f2 = sx4[2 * tp + 2];
        float4 f3 = sx4[2 * tp + 3];
        float v[16] = {f0.x,f0.y,f0.z,f0.w, f1.x,f1.y,f1.z,f1.w,
                       f2.x,f2.y,f2.z,f2.w, f3.x,f3.y,f3.z,f3.w};

        float h[8];
        #pragma unroll
        for (int j = 0; j < 8; ++j) {
            float a = bias0;
            #pragma unroll
            for (int k = 0; k < 7; ++k) a = fmaf(v[j + 1 + k], wk0[k], a);
            h[j] = gelu_leaky(a);
        }
        sL04[tp + 1] = make_float4(h[0]+h[1], h[2]+h[3], h[4]+h[5], h[6]+h[7]);
        sH04[tp + 1] = make_float4(h[0]-h[1], h[2]-h[3], h[4]-h[5], h[6]-h[7]);

        #pragma unroll
        for (int j = 0; j < 8; ++j) {
            float a = bias1;
            #pragma unroll
            for (int k = 0; k < 7; ++k) a = fmaf(v[j + 1 + k], wk1[k], a);
            h[j] = gelu_leaky(a);
        }
        sL14[tp + 1] = make_float4(h[0]+h[1], h[2]+h[3], h[4]+h[5], h[6]+h[7]);
        sH14[tp + 1] = make_float4(h[0]-h[1], h[2]-h[3], h[4]-h[5], h[6]-h[7]);
    }

    // phase-2 weights, both 1/sqrt2 folded in (w/2); phase-1 regs now dead
    float wL0[7], wL1[7], wH0[3], wH1[3];
    #pragma unroll
    for (int k = 0; k < 7; ++k) {
        wL0[k] = w2L[oc0 * 7 + k]     * 0.5f;
        wL1[k] = w2L[oc0 * 7 + 7 + k] * 0.5f;
    }
    #pragma unroll
    for (int k = 0; k < 3; ++k) {
        wH0[k] = w2H[oc0 * 3 + k]     * 0.5f;
        wH1[k] = w2H[oc0 * 3 + 3 + k] * 0.5f;
    }
    const float ws0 = wskip[oc0];
    const float ws1 = wskip[oc0 + 1];

    __syncthreads();

    // ---- phase 2: 4 pairs (8 outputs) / thread-iter, both channels ----
    float4* o0 = reinterpret_cast<float4*>(out + ((size_t)(b * 128 + oc0) << 12));
    float4* o1 = reinterpret_cast<float4*>(out + ((size_t)(b * 128 + oc0 + 1) << 12));

    #pragma unroll 1
    for (int p = 0; p < 2; ++p) {
        const int tp = tid + p * 256;          // pair base = 4*tp, out base = 8*tp
        float4 s0 = sx4[2 * tp + 1];           // x[8tp .. 8tp+3]
        float4 s1 = sx4[2 * tp + 2];           // x[8tp+4 .. 8tp+7]
        float xs[8] = {s0.x,s0.y,s0.z,s0.w, s1.x,s1.y,s1.z,s1.w};

        #pragma unroll
        for (int u = 0; u < 2; ++u) {
            const float4* L4 = u ? sL14 : sL04;
            const float4* H4 = u ? sH14 : sH04;
            const float* wL  = u ? wL1 : wL0;
            const float* wH  = u ? wH1 : wH0;
            const float  ws  = u ? ws1 : ws0;

            float4 l0 = L4[tp], l1 = L4[tp + 1], l2 = L4[tp + 2];
            float la[12] = {l0.x,l0.y,l0.z,l0.w, l1.x,l1.y,l1.z,l1.w,
                            l2.x,l2.y,l2.z,l2.w};          // la[i]=xL[4tp-4+i]
            float4 q0 = H4[tp], q1 = H4[tp + 1], q2 = H4[tp + 2];
            float hb[12] = {q0.x,q0.y,q0.z,q0.w, q1.x,q1.y,q1.z,q1.w,
                            q2.x,q2.y,q2.z,q2.w};          // hb[i]=xH[4tp-4+i]

            float o[8];
            #pragma unroll
            for (int q = 0; q < 4; ++q) {
                float yL = 0.f;
                #pragma unroll
                for (int j = 0; j < 7; ++j) yL = fmaf(wL[j], la[q + 1 + j], yL);
                float yH = 0.f;
                #pragma unroll
                for (int j = 0; j < 3; ++j) yH = fmaf(wH[j], hb[q + 3 + j], yH);
                float e = fmaf(xs[2 * q],     ws, yL + yH);
                float d = fmaf(xs[2 * q + 1], ws, yL - yH);
                o[2 * q]     = fmaxf(e, 0.01f * e);
                o[2 * q + 1] = fmaxf(d, 0.01f * d);
            }
            float4* dst = u ? o1 : o0;
            dst[2 * tp + 0] = make_float4(o[0], o[1], o[2], o[3]);
            dst[2 * tp + 1] = make_float4(o[4], o[5], o[6], o[7]);
        }
    }
}

extern "C" void kernel_launch(void* const* d_in, const int* in_sizes, int n_in,
                              void* d_out, int out_size) {
    const float* x     = (const float*)d_in[0];
    const float* w1    = (const float*)d_in[1];
    const float* g1    = (const float*)d_in[2];
    const float* b1    = (const float*)d_in[3];
    const float* m1    = (const float*)d_in[4];
    const float* v1    = (const float*)d_in[5];
    const float* w2L   = (const float*)d_in[6];
    const float* w2H   = (const float*)d_in[7];
    const float* wskip = (const float*)d_in[8];
    float* out = (float*)d_out;

    const int smem_bytes = SMEM_FLOATS * (int)sizeof(float);
    static bool attr_set = false;
    if (!attr_set) {
        cudaFuncSetAttribute(fused_block_wavelet_down,
                             cudaFuncAttributeMaxDynamicSharedMemorySize,
                             smem_bytes);
        attr_set = true;
    }
    fused_block_wavelet_down<<<64 * 64, 256, smem_bytes>>>(
        x, w1, g1, b1, m1, v1, w2L, w2H, wskip, out);
}

// round 5
// speedup vs baseline: 1.5933x; 1.5933x over previous
#include <cuda_runtime.h>
#include <cuda_bf16.h>

#define INV_SQRT2 0.70710678118654752440f

// Dynamic smem layout (floats):
//   sx  @ 0      len 4104 :  x[t]  at sx[t+4],  zeros [0..3], [4100..4103]
//   sL0 @ 4104   len 2056 :  xL[i] at +4,       zeros [0..3], [2052..2055]
//   sL1 @ 6160   len 2056
//   sH0 @ 8216   len 2052 :  xH[i] at +2,       zeros [0..1], [2050..2051]
//   sH1 @ 10268  len 2052
// total 12320 floats = 49280 bytes
#define SMEM_FLOATS 12320

__device__ __forceinline__ float gelu_leaky(float a) {
    float t = 0.5f * a;
    a = fmaf(t, erff(a * INV_SQRT2), t);   // exact GELU: 0.5a + 0.5a*erf(a/sqrt2)
    return fmaxf(a, 0.01f * a);            // LeakyReLU(0.01)
}

// One CTA per (b, cin); produces output channels 2*cin and 2*cin+1,
// sharing every x-window / skip load between the two channels.
// BN folded into w1; both 1/sqrt2 Haar factors folded into w2L/w2H (=> w/2).
__global__ __launch_bounds__(256, 4)
void fused_block_wavelet_down(
    const float* __restrict__ x,      // (64, 64, 4096)
    const float* __restrict__ w1,     // (128, 1, 7)
    const float* __restrict__ g1,
    const float* __restrict__ b1,
    const float* __restrict__ m1,
    const float* __restrict__ v1,
    const float* __restrict__ w2L,    // (128, 1, 7)
    const float* __restrict__ w2H,    // (128, 1, 3)
    const float* __restrict__ wskip,  // (128, 1, 1)
    float* __restrict__ out)          // (64, 128, 4096)
{
    extern __shared__ float smem[];
    float* sx  = smem;
    float* sL0 = smem + 4104;
    float* sL1 = smem + 6160;
    float* sH0 = smem + 8216;
    float* sH1 = smem + 10268;

    const int tid = threadIdx.x;
    const int b   = blockIdx.x >> 6;
    const int cin = blockIdx.x & 63;
    const int oc0 = 2 * cin;

    // zero pad cells (vector stores; never overlap real data)
    if (tid == 0) *reinterpret_cast<float4*>(sx)          = make_float4(0,0,0,0);
    if (tid == 1) *reinterpret_cast<float4*>(sx + 4100)   = make_float4(0,0,0,0);
    if (tid == 2) *reinterpret_cast<float4*>(sL0)         = make_float4(0,0,0,0);
    if (tid == 3) *reinterpret_cast<float4*>(sL0 + 2052)  = make_float4(0,0,0,0);
    if (tid == 4) *reinterpret_cast<float4*>(sL1)         = make_float4(0,0,0,0);
    if (tid == 5) *reinterpret_cast<float4*>(sL1 + 2052)  = make_float4(0,0,0,0);
    if (tid == 6) *reinterpret_cast<float2*>(sH0)         = make_float2(0,0);
    if (tid == 7) *reinterpret_cast<float2*>(sH0 + 2050)  = make_float2(0,0);
    if (tid == 8) *reinterpret_cast<float2*>(sH1)         = make_float2(0,0);
    if (tid == 9) *reinterpret_cast<float2*>(sH1 + 2050)  = make_float2(0,0);

    // load x row: LDG.128 -> STS.128, lane-contiguous
    {
        const float4* x4 = reinterpret_cast<const float4*>(
            x + ((size_t)(b * 64 + cin) << 12));
        float4* sxw = reinterpret_cast<float4*>(sx + 4);
        #pragma unroll
        for (int p = 0; p < 4; ++p)
            sxw[tid + p * 256] = x4[tid + p * 256];
    }

    // phase-1 weights, BN folded: h = conv(x, w1*inv) + bias
    float wk0[7], wk1[7], bias0, bias1;
    {
        const float inv0 = g1[oc0]     * rsqrtf(v1[oc0]     + 1e-5f);
        const float inv1 = g1[oc0 + 1] * rsqrtf(v1[oc0 + 1] + 1e-5f);
        #pragma unroll
        for (int k = 0; k < 7; ++k) {
            wk0[k] = w1[oc0 * 7 + k]     * inv0;
            wk1[k] = w1[oc0 * 7 + 7 + k] * inv1;
        }
        bias0 = b1[oc0]     - m1[oc0]     * inv0;
        bias1 = b1[oc0 + 1] - m1[oc0 + 1] * inv1;
    }

    __syncthreads();

    // ---- phase 1: conv7(+BN) + GELU + leaky + unscaled Haar, both channels ----
    {
        const float4* sxp = reinterpret_cast<const float4*>(sx) + tid;
        float2* sL0p = reinterpret_cast<float2*>(sL0) + tid + 2;
        float2* sL1p = reinterpret_cast<float2*>(sL1) + tid + 2;
        float2* sH0p = reinterpret_cast<float2*>(sH0) + tid + 1;
        float2* sH1p = reinterpret_cast<float2*>(sH1) + tid + 1;

        #pragma unroll 1
        for (int p = 0; p < 4; ++p) {
            float4 f0 = sxp[0];                 // conflict-free, lane-contiguous
            float4 f1 = sxp[1];
            float4 f2 = sxp[2];
            float v[12] = {f0.x,f0.y,f0.z,f0.w, f1.x,f1.y,f1.z,f1.w,
                           f2.x,f2.y,f2.z,f2.w};

            float h[4];
            #pragma unroll
            for (int j = 0; j < 4; ++j) {
                float a = bias0;
                #pragma unroll
                for (int k = 0; k < 7; ++k) a = fmaf(v[1 + j + k], wk0[k], a);
                h[j] = gelu_leaky(a);
            }
            sL0p[0] = make_float2(h[0] + h[1], h[2] + h[3]);
            sH0p[0] = make_float2(h[0] - h[1], h[2] - h[3]);

            #pragma unroll
            for (int j = 0; j < 4; ++j) {
                float a = bias1;
                #pragma unroll
                for (int k = 0; k < 7; ++k) a = fmaf(v[1 + j + k], wk1[k], a);
                h[j] = gelu_leaky(a);
            }
            sL1p[0] = make_float2(h[0] + h[1], h[2] + h[3]);
            sH1p[0] = make_float2(h[0] - h[1], h[2] - h[3]);

            sxp  += 256;
            sL0p += 256; sL1p += 256;
            sH0p += 256; sH1p += 256;
        }
    }

    // phase-2 weights, both 1/sqrt2 folded (w/2); phase-1 weight regs dead
    float wL0[7], wL1[7], wH0[3], wH1[3];
    #pragma unroll
    for (int k = 0; k < 7; ++k) {
        wL0[k] = w2L[oc0 * 7 + k]     * 0.5f;
        wL1[k] = w2L[oc0 * 7 + 7 + k] * 0.5f;
    }
    #pragma unroll
    for (int k = 0; k < 3; ++k) {
        wH0[k] = w2H[oc0 * 3 + k]     * 0.5f;
        wH1[k] = w2H[oc0 * 3 + 3 + k] * 0.5f;
    }
    const float ws0 = wskip[oc0];
    const float ws1 = wskip[oc0 + 1];

    __syncthreads();

    // ---- phase 2: conv7L/conv3H + merge + skip + leaky, both channels ----
    {
        const float4* skp = reinterpret_cast<const float4*>(sx) + tid + 1;
        const float2* L0p = reinterpret_cast<const float2*>(sL0) + tid;
        const float2* L1p = reinterpret_cast<const float2*>(sL1) + tid;
        const float2* H0p = reinterpret_cast<const float2*>(sH0) + tid;
        const float2* H1p = reinterpret_cast<const float2*>(sH1) + tid;
        float4* o0p = reinterpret_cast<float4*>(
            out + ((size_t)(b * 128 + oc0) << 12)) + tid;
        float4* o1p = o0p + 1024;              // next channel row = 4096 floats

        #pragma unroll 1
        for (int p = 0; p < 4; ++p) {
            const float4 sk = skp[0];          // x[4tp..4tp+3], conflict-free

            #pragma unroll
            for (int u = 0; u < 2; ++u) {
                const float2* Lp = u ? L1p : L0p;
                const float2* Hp = u ? H1p : H0p;
                const float* wL  = u ? wL1 : wL0;
                const float* wH  = u ? wH1 : wH0;
                const float  ws  = u ? ws1 : ws0;

                float la[10];
                #pragma unroll
                for (int c = 0; c < 5; ++c) {
                    float2 t = Lp[c];
                    la[2 * c] = t.x; la[2 * c + 1] = t.y;
                }
                float ha[6];
                #pragma unroll
                for (int c = 0; c < 3; ++c) {
                    float2 t = Hp[c];
                    ha[2 * c] = t.x; ha[2 * c + 1] = t.y;
                }

                float yL0 = 0.f, yL1 = 0.f;
                #pragma unroll
                for (int j = 0; j < 7; ++j) {
                    yL0 = fmaf(wL[j], la[1 + j], yL0);
                    yL1 = fmaf(wL[j], la[2 + j], yL1);
                }
                float yH0 = 0.f, yH1 = 0.f;
                #pragma unroll
                for (int j = 0; j < 3; ++j) {
                    yH0 = fmaf(wH[j], ha[1 + j], yH0);
                    yH1 = fmaf(wH[j], ha[2 + j], yH1);
                }

                float4 o;
                o.x = fmaf(sk.x, ws, yL0 + yH0);
                o.y = fmaf(sk.y, ws, yL0 - yH0);
                o.z = fmaf(sk.z, ws, yL1 + yH1);
                o.w = fmaf(sk.w, ws, yL1 - yH1);
                o.x = fmaxf(o.x, 0.01f * o.x);
                o.y = fmaxf(o.y, 0.01f * o.y);
                o.z = fmaxf(o.z, 0.01f * o.z);
                o.w = fmaxf(o.w, 0.01f * o.w);
                (u ? o1p : o0p)[0] = o;
            }
            skp += 256;
            L0p += 256; L1p += 256;
            H0p += 256; H1p += 256;
            o0p += 256; o1p += 256;
        }
    }
}

extern "C" void kernel_launch(void* const* d_in, const int* in_sizes, int n_in,
                              void* d_out, int out_size) {
    const float* x     = (const float*)d_in[0];
    const float* w1    = (const float*)d_in[1];
    const float* g1    = (const float*)d_in[2];
    const float* b1    = (const float*)d_in[3];
    const float* m1    = (const float*)d_in[4];
    const float* v1    = (const float*)d_in[5];
    const float* w2L   = (const float*)d_in[6];
    const float* w2H   = (const float*)d_in[7];
    const float* wskip = (const float*)d_in[8];
    float* out = (float*)d_out;

    const int smem_bytes = SMEM_FLOATS * (int)sizeof(float);
    static bool attr_set = false;
    if (!attr_set) {
        cudaFuncSetAttribute(fused_block_wavelet_down,
                             cudaFuncAttributeMaxDynamicSharedMemorySize,
                             smem_bytes);
        attr_set = true;
    }
    fused_block_wavelet_down<<<64 * 64, 256, smem_bytes>>>(
        x, w1, g1, b1, m1, v1, w2L, w2H, wskip, out);
}

// round 6
// speedup vs baseline: 1.9659x; 1.2339x over previous
#include <cuda_runtime.h>
#include <cuda_bf16.h>

#define INV_SQRT2 0.70710678118654752440f

// Dynamic smem layout (floats):
//   sx  @ 0      len 4104 :  x[t]  at sx[t+4],  zeros [0..3], [4100..4103]
//   sL0 @ 4104   len 2056 :  xL[i] at +4,       zeros [0..3], [2052..2055]
//   sL1 @ 6160   len 2056
//   sH0 @ 8216   len 2052 :  xH[i] at +2,       zeros [0..1], [2050..2051]
//   sH1 @ 10268  len 2052
// total 12320 floats = 49280 bytes
#define SMEM_FLOATS 12320

typedef unsigned long long ull;

// ---- f32x2 packed helpers (sm_100+) ----
__device__ __forceinline__ ull pack2(float lo, float hi) {
    ull r; asm("mov.b64 %0, {%1, %2};" : "=l"(r) : "f"(lo), "f"(hi)); return r;
}
__device__ __forceinline__ float2 unpack2(ull v) {
    float2 r; asm("mov.b64 {%0, %1}, %2;" : "=f"(r.x), "=f"(r.y) : "l"(v)); return r;
}
__device__ __forceinline__ ull fma2_(ull a, ull b, ull c) {
    ull r; asm("fma.rn.f32x2 %0, %1, %2, %3;" : "=l"(r) : "l"(a), "l"(b), "l"(c)); return r;
}
__device__ __forceinline__ ull mul2_(ull a, ull b) {
    ull r; asm("mul.rn.f32x2 %0, %1, %2;" : "=l"(r) : "l"(a), "l"(b)); return r;
}
__device__ __forceinline__ ull add2_(ull a, ull b) {
    ull r; asm("add.rn.f32x2 %0, %1, %2;" : "=l"(r) : "l"(a), "l"(b)); return r;
}
__device__ __forceinline__ ull abs2_(ull a) {   // clear sign bits, both lanes
    ull r; asm("and.b64 %0, %1, 0x7FFFFFFF7FFFFFFF;" : "=l"(r) : "l"(a)); return r;
}
__device__ __forceinline__ ull neg2_(ull a) {   // flip sign bits, both lanes
    ull r; asm("xor.b64 %0, %1, 0x8000000080000000;" : "=l"(r) : "l"(a)); return r;
}
__device__ __forceinline__ float tanh_approx(float x) {
    float y; asm("tanh.approx.f32 %0, %1;" : "=f"(y) : "f"(x)); return y;
}

// One CTA per (b, cin); produces output channels 2*cin and 2*cin+1.
// BN folded into w1; 1/sqrt2 Haar factors folded into w2L/w2H (=> w/2).
// GELU+leaky evaluated channel-paired in f32x2 with HW tanh.
__global__ __launch_bounds__(256, 4)
void fused_block_wavelet_down(
    const float* __restrict__ x,      // (64, 64, 4096)
    const float* __restrict__ w1,     // (128, 1, 7)
    const float* __restrict__ g1,
    const float* __restrict__ b1,
    const float* __restrict__ m1,
    const float* __restrict__ v1,
    const float* __restrict__ w2L,    // (128, 1, 7)
    const float* __restrict__ w2H,    // (128, 1, 3)
    const float* __restrict__ wskip,  // (128, 1, 1)
    float* __restrict__ out)          // (64, 128, 4096)
{
    extern __shared__ float smem[];
    float* sx  = smem;
    float* sL0 = smem + 4104;
    float* sL1 = smem + 6160;
    float* sH0 = smem + 8216;
    float* sH1 = smem + 10268;

    const int tid = threadIdx.x;
    const int b   = blockIdx.x >> 6;
    const int cin = blockIdx.x & 63;
    const int oc0 = 2 * cin;

    // zero pad cells (vector stores; never overlap real data)
    if (tid == 0) *reinterpret_cast<float4*>(sx)          = make_float4(0,0,0,0);
    if (tid == 1) *reinterpret_cast<float4*>(sx + 4100)   = make_float4(0,0,0,0);
    if (tid == 2) *reinterpret_cast<float4*>(sL0)         = make_float4(0,0,0,0);
    if (tid == 3) *reinterpret_cast<float4*>(sL0 + 2052)  = make_float4(0,0,0,0);
    if (tid == 4) *reinterpret_cast<float4*>(sL1)         = make_float4(0,0,0,0);
    if (tid == 5) *reinterpret_cast<float4*>(sL1 + 2052)  = make_float4(0,0,0,0);
    if (tid == 6) *reinterpret_cast<float2*>(sH0)         = make_float2(0,0);
    if (tid == 7) *reinterpret_cast<float2*>(sH0 + 2050)  = make_float2(0,0);
    if (tid == 8) *reinterpret_cast<float2*>(sH1)         = make_float2(0,0);
    if (tid == 9) *reinterpret_cast<float2*>(sH1 + 2050)  = make_float2(0,0);

    // load x row: LDG.128 -> STS.128, lane-contiguous
    {
        const float4* x4 = reinterpret_cast<const float4*>(
            x + ((size_t)(b * 64 + cin) << 12));
        float4* sxw = reinterpret_cast<float4*>(sx + 4);
        #pragma unroll
        for (int p = 0; p < 4; ++p)
            sxw[tid + p * 256] = x4[tid + p * 256];
    }

    // phase-1 weights, BN folded: h = conv(x, w1*inv) + bias
    float wk0[7], wk1[7], bias0, bias1;
    {
        const float inv0 = g1[oc0]     * rsqrtf(v1[oc0]     + 1e-5f);
        const float inv1 = g1[oc0 + 1] * rsqrtf(v1[oc0 + 1] + 1e-5f);
        #pragma unroll
        for (int k = 0; k < 7; ++k) {
            wk0[k] = w1[oc0 * 7 + k]     * inv0;
            wk1[k] = w1[oc0 * 7 + 7 + k] * inv1;
        }
        bias0 = b1[oc0]     - m1[oc0]     * inv0;
        bias1 = b1[oc0 + 1] - m1[oc0 + 1] * inv1;
    }

    // packed constants for the activation
    const ull C_HALF = pack2(0.5f, 0.5f);
    const ull C_K0   = pack2(0.79788456080286536f, 0.79788456080286536f); // sqrt(2/pi)
    const ull C_K1   = pack2(0.044715f, 0.044715f);
    const ull C_A    = pack2(0.505f, 0.505f);   // leaky: max(g,.01g)=.505g+.495|g|
    const ull C_B    = pack2(0.495f, 0.495f);

    __syncthreads();

    // ---- phase 1: scalar conv7(+BN), packed GELU+leaky, packed Haar ----
    {
        const float4* sxp = reinterpret_cast<const float4*>(sx) + tid;
        float2* sL0p = reinterpret_cast<float2*>(sL0) + tid + 2;
        float2* sL1p = reinterpret_cast<float2*>(sL1) + tid + 2;
        float2* sH0p = reinterpret_cast<float2*>(sH0) + tid + 1;
        float2* sH1p = reinterpret_cast<float2*>(sH1) + tid + 1;

        #pragma unroll 1
        for (int p = 0; p < 4; ++p) {
            float4 f0 = sxp[0];                 // conflict-free, lane-contiguous
            float4 f1 = sxp[1];
            float4 f2 = sxp[2];
            float v[12] = {f0.x,f0.y,f0.z,f0.w, f1.x,f1.y,f1.z,f1.w,
                           f2.x,f2.y,f2.z,f2.w};

            ull hp[4];
            #pragma unroll
            for (int j = 0; j < 4; ++j) {
                float a0 = bias0, a1 = bias1;
                #pragma unroll
                for (int k = 0; k < 7; ++k) {
                    a0 = fmaf(v[1 + j + k], wk0[k], a0);
                    a1 = fmaf(v[1 + j + k], wk1[k], a1);
                }
                // packed tanh-GELU + leaky on {a0, a1}
                ull ap = pack2(a0, a1);
                ull t  = mul2_(ap, C_HALF);          // 0.5a
                ull x2 = mul2_(ap, ap);              // a^2
                ull t0 = mul2_(ap, C_K0);            // k0*a
                ull t1 = mul2_(t0, C_K1);            // k0*k1*a
                ull u  = fma2_(t1, x2, t0);          // k0*a*(1+k1*a^2)
                float2 uv = unpack2(u);
                ull th = pack2(tanh_approx(uv.x), tanh_approx(uv.y));
                ull g  = fma2_(t, th, t);            // 0.5a(1+tanh)
                hp[j]  = fma2_(g, C_A, mul2_(abs2_(g), C_B)); // leaky
            }

            // packed Haar: lanes stay {ch0, ch1}
            ull sLa = add2_(hp[0], hp[1]);
            ull sHa = add2_(hp[0], neg2_(hp[1]));
            ull sLb = add2_(hp[2], hp[3]);
            ull sHb = add2_(hp[2], neg2_(hp[3]));
            float2 la  = unpack2(sLa), lb  = unpack2(sLb);
            float2 ha_ = unpack2(sHa), hb_ = unpack2(sHb);
            sL0p[0] = make_float2(la.x,  lb.x);
            sL1p[0] = make_float2(la.y,  lb.y);
            sH0p[0] = make_float2(ha_.x, hb_.x);
            sH1p[0] = make_float2(ha_.y, hb_.y);

            sxp  += 256;
            sL0p += 256; sL1p += 256;
            sH0p += 256; sH1p += 256;
        }
    }

    // phase-2 weights, both 1/sqrt2 folded (w/2); phase-1 weight regs dead
    float wL0[7], wL1[7], wH0[3], wH1[3];
    #pragma unroll
    for (int k = 0; k < 7; ++k) {
        wL0[k] = w2L[oc0 * 7 + k]     * 0.5f;
        wL1[k] = w2L[oc0 * 7 + 7 + k] * 0.5f;
    }
    #pragma unroll
    for (int k = 0; k < 3; ++k) {
        wH0[k] = w2H[oc0 * 3 + k]     * 0.5f;
        wH1[k] = w2H[oc0 * 3 + 3 + k] * 0.5f;
    }
    const float ws0 = wskip[oc0];
    const float ws1 = wskip[oc0 + 1];

    __syncthreads();

    // ---- phase 2: conv7L/conv3H + merge + skip + leaky, both channels ----
    {
        const float4* skp = reinterpret_cast<const float4*>(sx) + tid + 1;
        const float2* L0p = reinterpret_cast<const float2*>(sL0) + tid;
        const float2* L1p = reinterpret_cast<const float2*>(sL1) + tid;
        const float2* H0p = reinterpret_cast<const float2*>(sH0) + tid;
        const float2* H1p = reinterpret_cast<const float2*>(sH1) + tid;
        float4* o0p = reinterpret_cast<float4*>(
            out + ((size_t)(b * 128 + oc0) << 12)) + tid;
        float4* o1p = o0p + 1024;              // next channel row = 4096 floats

        #pragma unroll 1
        for (int p = 0; p < 4; ++p) {
            const float4 sk = skp[0];          // x[4tp..4tp+3], conflict-free

            #pragma unroll
            for (int u = 0; u < 2; ++u) {
                const float2* Lp = u ? L1p : L0p;
                const float2* Hp = u ? H1p : H0p;
                const float* wL  = u ? wL1 : wL0;
                const float* wH  = u ? wH1 : wH0;
                const float  ws  = u ? ws1 : ws0;

                float la[10];
                #pragma unroll
                for (int c = 0; c < 5; ++c) {
                    float2 t = Lp[c];
                    la[2 * c] = t.x; la[2 * c + 1] = t.y;
                }
                float ha[6];
                #pragma unroll
                for (int c = 0; c < 3; ++c) {
                    float2 t = Hp[c];
                    ha[2 * c] = t.x; ha[2 * c + 1] = t.y;
                }

                float yL0 = 0.f, yL1 = 0.f;
                #pragma unroll
                for (int j = 0; j < 7; ++j) {
                    yL0 = fmaf(wL[j], la[1 + j], yL0);
                    yL1 = fmaf(wL[j], la[2 + j], yL1);
                }
                float yH0 = 0.f, yH1 = 0.f;
                #pragma unroll
                for (int j = 0; j < 3; ++j) {
                    yH0 = fmaf(wH[j], ha[1 + j], yH0);
                    yH1 = fmaf(wH[j], ha[2 + j], yH1);
                }

                float4 o;
                o.x = fmaf(sk.x, ws, yL0 + yH0);
                o.y = fmaf(sk.y, ws, yL0 - yH0);
                o.z = fmaf(sk.z, ws, yL1 + yH1);
                o.w = fmaf(sk.w, ws, yL1 - yH1);
                o.x = fmaxf(o.x, 0.01f * o.x);
                o.y = fmaxf(o.y, 0.01f * o.y);
                o.z = fmaxf(o.z, 0.01f * o.z);
                o.w = fmaxf(o.w, 0.01f * o.w);
                (u ? o1p : o0p)[0] = o;
            }
            skp += 256;
            L0p += 256; L1p += 256;
            H0p += 256; H1p += 256;
            o0p += 256; o1p += 256;
        }
    }
}

extern "C" void kernel_launch(void* const* d_in, const int* in_sizes, int n_in,
                              void* d_out, int out_size) {
    const float* x     = (const float*)d_in[0];
    const float* w1    = (const float*)d_in[1];
    const float* g1    = (const float*)d_in[2];
    const float* b1    = (const float*)d_in[3];
    const float* m1    = (const float*)d_in[4];
    const float* v1    = (const float*)d_in[5];
    const float* w2L   = (const float*)d_in[6];
    const float* w2H   = (const float*)d_in[7];
    const float* wskip = (const float*)d_in[8];
    float* out = (float*)d_out;

    const int smem_bytes = SMEM_FLOATS * (int)sizeof(float);
    static bool attr_set = false;
    if (!attr_set) {
        cudaFuncSetAttribute(fused_block_wavelet_down,
                             cudaFuncAttributeMaxDynamicSharedMemorySize,
                             smem_bytes);
        attr_set = true;
    }
    fused_block_wavelet_down<<<64 * 64, 256, smem_bytes>>>(
        x, w1, g1, b1, m1, v1, w2L, w2H, wskip, out);
}